// round 2
// baseline (speedup 1.0000x reference)
#include <cuda_runtime.h>

#define Cc 256
#define Hh 56
#define Ww 56

// Scratch (no allocs allowed): premultiplied+transposed weights, SE intermediates.
__device__ float g_wpt[256 * 9 * 256];   // [ci][tap][co]  = weight*A_w, 2.36 MB
__device__ float g_w1t[256 * 9 * 16];    // [ci][tap][co]  se_w1 transposed
__device__ float g_t[8 * 16 * 56 * 56];  // relu(conv1) output
__device__ float g_a[8 * 56 * 56];       // attention map

__device__ __forceinline__ void ffma2(unsigned long long& d, unsigned long long a,
                                      unsigned long long b) {
    asm("fma.rn.f32x2 %0, %1, %2, %0;" : "+l"(d) : "l"(a), "l"(b));
}

__device__ __forceinline__ unsigned long long dup2(float v) {
    unsigned long long u;
    unsigned int r = __float_as_uint(v);
    asm("mov.b64 %0, {%1, %1};" : "=l"(u) : "r"(r));
    return u;
}

// ---------------------------------------------------------------------------
// Prep: g_wpt[ci*2304 + tap*256 + co] = weight[co,ci,tap] * A_w[ci,tap]
//       g_w1t[ci*144 + tap*16 + co]   = se_w1[co,ci,tap]
// ---------------------------------------------------------------------------
__global__ void prep_weights(const float* __restrict__ weight,
                             const float* __restrict__ A_w,
                             const float* __restrict__ se_w1) {
    int idx = blockIdx.x * 256 + threadIdx.x;
    if (idx < 589824) {
        int co = idx & 255;
        int tap = (idx >> 8) % 9;
        int ci = idx / 2304;
        g_wpt[idx] = weight[co * 2304 + ci * 9 + tap] * A_w[ci * 9 + tap];
    } else if (idx < 589824 + 36864) {
        int i2 = idx - 589824;
        int co = i2 & 15;
        int tap = (i2 >> 4) % 9;
        int ci = i2 / 144;
        g_w1t[i2] = se_w1[co * 2304 + ci * 9 + tap];
    }
}

// ---------------------------------------------------------------------------
// SE conv1: t = relu(conv3x3(x, se_w1))   [8,16,56,56]
// Block: 256 thr = 4 co-groups(4 co) x 64 spatial; tile 4 rows x 32 cols.
// ---------------------------------------------------------------------------
__global__ __launch_bounds__(256) void conv_se1(const float* __restrict__ x) {
    __shared__ __align__(16) float xs[6][35];
    __shared__ __align__(16) float ws[9][16];
    int tid = threadIdx.x;
    int ct = tid >> 6;          // co group 0..3
    int s = tid & 63;
    int row = s >> 4;           // 0..3
    int col0 = (s & 15) << 1;   // 0..30
    int wt = blockIdx.x, ht = blockIdx.y, b = blockIdx.z;
    int h0 = ht * 4, w0 = wt * 32;
    float acc[4][2] = {};
    const float* xb = x + b * Cc * Hh * Ww;

    for (int ci = 0; ci < Cc; ci++) {
        const float* xc = xb + ci * Hh * Ww;
        if (tid < 204) {  // 6 x 34 halo tile
            int r = tid / 34, c = tid % 34;
            int gh = h0 - 1 + r, gw = w0 - 1 + c;
            xs[r][c] = (gh >= 0 && gh < Hh && gw >= 0 && gw < Ww) ? xc[gh * Ww + gw] : 0.f;
        }
        if (tid < 144) ws[tid >> 4][tid & 15] = g_w1t[ci * 144 + tid];
        __syncthreads();

        float xr[3][4];
#pragma unroll
        for (int dy = 0; dy < 3; dy++)
#pragma unroll
            for (int p = 0; p < 4; p++) xr[dy][p] = xs[row + dy][col0 + p];

#pragma unroll
        for (int dy = 0; dy < 3; dy++)
#pragma unroll
            for (int dx = 0; dx < 3; dx++) {
                float4 wv = *(const float4*)&ws[dy * 3 + dx][ct << 2];
#pragma unroll
                for (int p = 0; p < 2; p++) {
                    float xv = xr[dy][p + dx];
                    acc[0][p] += wv.x * xv;
                    acc[1][p] += wv.y * xv;
                    acc[2][p] += wv.z * xv;
                    acc[3][p] += wv.w * xv;
                }
            }
        __syncthreads();
    }

    int h = h0 + row;
#pragma unroll
    for (int j = 0; j < 4; j++) {
        int co = (ct << 2) + j;
        float* tp = g_t + ((b * 16 + co) * Hh + h) * Ww;
#pragma unroll
        for (int p = 0; p < 2; p++) {
            int w = w0 + col0 + p;
            if (w < Ww) tp[w] = fmaxf(acc[j][p], 0.f);
        }
    }
}

// ---------------------------------------------------------------------------
// SE conv2 + sigmoid: a = sigmoid(conv3x3(t, se_w2))   [8,56,56]
// One block per (b,h) row, one thread per w.
// ---------------------------------------------------------------------------
__global__ __launch_bounds__(64) void conv_se2(const float* __restrict__ se_w2) {
    __shared__ float ws[144];
    int tid = threadIdx.x;
    int bh = blockIdx.x;
    int b = bh / Hh, h = bh % Hh;
    for (int i = tid; i < 144; i += 64) ws[i] = se_w2[i];
    __syncthreads();
    if (tid >= Ww) return;
    int w = tid;
    float sum = 0.f;
    for (int ci = 0; ci < 16; ci++) {
        const float* tp = g_t + ((b * 16 + ci) * Hh) * Ww;
#pragma unroll
        for (int dy = 0; dy < 3; dy++) {
            int gh = h + dy - 1;
            if (gh < 0 || gh >= Hh) continue;
#pragma unroll
            for (int dx = 0; dx < 3; dx++) {
                int gw = w + dx - 1;
                if (gw < 0 || gw >= Ww) continue;
                sum += tp[gh * Ww + gw] * ws[ci * 9 + dy * 3 + dx];
            }
        }
    }
    g_a[b * Hh * Ww + h * Ww + w] = 1.f / (1.f + __expf(-sum));
}

// ---------------------------------------------------------------------------
// Main conv: out = conv3x3(x, wpt) * a
// Block: 256 thr = 8 co-threads(8 co via 4 f32x2 pairs) x 32 spatial.
// Tile: 64 co x (8 rows x 32 cols). Grid (2,7,32): wt, ht, b*4+cog.
// xs stride 35 -> conflict-free: bank = (3*row + 8*(lane&3) + k) mod 32, bijective.
// ---------------------------------------------------------------------------
__global__ __launch_bounds__(256) void main_conv(const float* __restrict__ x,
                                                 float* __restrict__ out) {
    __shared__ __align__(16) float xs[10][35];
    __shared__ __align__(16) float ws[9][64];
    int tid = threadIdx.x;
    int cot = tid >> 5;              // 0..7 (one warp per co sub-group)
    int lane = tid & 31;
    int row = lane >> 2;             // 0..7
    int col0 = (lane & 3) << 3;      // 0,8,16,24
    int wt = blockIdx.x, ht = blockIdx.y;
    int b = blockIdx.z >> 2, cog = blockIdx.z & 3;
    int h0 = ht * 8, w0 = wt * 32;
    int co_base = cog * 64;

    unsigned long long acc[4][8];
#pragma unroll
    for (int j = 0; j < 4; j++)
#pragma unroll
        for (int p = 0; p < 8; p++) acc[j][p] = 0ULL;

    const float* xb = x + b * Cc * Hh * Ww;

    for (int ci = 0; ci < Cc; ci++) {
        const float* xc = xb + ci * Hh * Ww;
        for (int i = tid; i < 340; i += 256) {  // 10 x 34 halo tile
            int r = i / 34, c = i % 34;
            int gh = h0 - 1 + r, gw = w0 - 1 + c;
            xs[r][c] = (gh >= 0 && gh < Hh && gw >= 0 && gw < Ww) ? xc[gh * Ww + gw] : 0.f;
        }
        const float* wc = g_wpt + ci * 2304 + co_base;
        for (int i = tid; i < 576; i += 256) {
            ws[i >> 6][i & 63] = wc[((i >> 6) << 8) + (i & 63)];
        }
        __syncthreads();

#pragma unroll 1
        for (int dy = 0; dy < 3; dy++) {
            unsigned long long xd[10];
#pragma unroll
            for (int p = 0; p < 10; p++) xd[p] = dup2(xs[row + dy][col0 + p]);
#pragma unroll
            for (int dx = 0; dx < 3; dx++) {
                const unsigned long long* w2 =
                    (const unsigned long long*)&ws[dy * 3 + dx][cot << 3];
                unsigned long long wv0 = w2[0], wv1 = w2[1], wv2 = w2[2], wv3 = w2[3];
#pragma unroll
                for (int p = 0; p < 8; p++) {
                    unsigned long long xv = xd[p + dx];
                    ffma2(acc[0][p], wv0, xv);
                    ffma2(acc[1][p], wv1, xv);
                    ffma2(acc[2][p], wv2, xv);
                    ffma2(acc[3][p], wv3, xv);
                }
            }
        }
        __syncthreads();
    }

    // Epilogue: unpack pairs, multiply by attention map, store.
    int h = h0 + row;
    const float* ab = g_a + b * Hh * Ww + h * Ww;
    float av[8];
#pragma unroll
    for (int p = 0; p < 8; p++) {
        int w = w0 + col0 + p;
        av[p] = (w < Ww) ? ab[w] : 0.f;
    }
#pragma unroll
    for (int j2 = 0; j2 < 4; j2++) {
        int co = co_base + (cot << 3) + (j2 << 1);
        float* o0 = out + ((b * Cc + co) * Hh + h) * Ww;
        float* o1 = o0 + Hh * Ww;
#pragma unroll
        for (int p = 0; p < 8; p++) {
            int w = w0 + col0 + p;
            if (w < Ww) {
                float lo = __uint_as_float((unsigned int)acc[j2][p]);
                float hi = __uint_as_float((unsigned int)(acc[j2][p] >> 32));
                o0[w] = lo * av[p];
                o1[w] = hi * av[p];
            }
        }
    }
}

// ---------------------------------------------------------------------------
extern "C" void kernel_launch(void* const* d_in, const int* in_sizes, int n_in,
                              void* d_out, int out_size) {
    const float* x = (const float*)d_in[0];       // [8,256,56,56]
    const float* weight = (const float*)d_in[1];  // [256,256,3,3]
    const float* A_w = (const float*)d_in[2];     // [1,256,3,3]
    const float* se_w1 = (const float*)d_in[3];   // [16,256,3,3]
    const float* se_w2 = (const float*)d_in[4];   // [1,16,3,3]
    float* out = (float*)d_out;                   // [8,256,56,56]

    prep_weights<<<(589824 + 36864 + 255) / 256, 256>>>(weight, A_w, se_w1);
    conv_se1<<<dim3(2, 14, 8), 256>>>(x);
    conv_se2<<<8 * Hh, 64>>>(se_w2);
    main_conv<<<dim3(2, 7, 32), 256>>>(x, out);
}

// round 3
// speedup vs baseline: 1.6776x; 1.6776x over previous
#include <cuda_runtime.h>

#define Cc 256
#define Hh 56
#define Ww 56
#define XPR 80   // padded row stride (floats)
#define XPH 58   // padded rows

// Scratch (device globals; zero-initialized at load, no allocs).
__device__ float g_xp[8 * 256 * XPH * XPR];      // padded x, cols>=58 stay 0
__device__ float g_wpt2[4][256][9][64];          // [cog][ci][tap][co64] = weight*A_w
__device__ float g_w1t[256 * 9 * 16];            // [ci][tap][co] se_w1 transposed
__device__ float g_t[8 * 16 * 56 * 56];          // relu(conv1)
__device__ float g_a[8 * 56 * 56];               // attention map

__device__ __forceinline__ void ffma2(unsigned long long& d, unsigned long long a,
                                      unsigned long long b) {
    asm("fma.rn.f32x2 %0, %1, %2, %0;" : "+l"(d) : "l"(a), "l"(b));
}
__device__ __forceinline__ unsigned long long dup2(float v) {
    unsigned long long u;
    unsigned int r = __float_as_uint(v);
    asm("mov.b64 %0, {%1, %1};" : "=l"(u) : "r"(r));
    return u;
}
__device__ __forceinline__ void cp16(void* s, const void* g) {
    unsigned sa = (unsigned)__cvta_generic_to_shared(s);
    asm volatile("cp.async.cg.shared.global [%0], [%1], 16;" ::"r"(sa), "l"(g));
}
#define CP_COMMIT() asm volatile("cp.async.commit_group;")
#define CP_WAIT0() asm volatile("cp.async.wait_group 0;")

// ---------------------------------------------------------------------------
// Pad x into g_xp (zero border). Cols >= 58 never written -> stay 0.
// ---------------------------------------------------------------------------
__global__ void pad_x(const float* __restrict__ x) {
    int idx = blockIdx.x * 256 + threadIdx.x;
    if (idx >= 8 * 256 * XPH * XPH) return;
    int w = idx % XPH;
    int h = (idx / XPH) % XPH;
    int c = (idx / (XPH * XPH)) % 256;
    int b = idx / (XPH * XPH * 256);
    float v = 0.f;
    if (h >= 1 && h < 57 && w >= 1 && w < 57)
        v = x[((b * 256 + c) * Hh + (h - 1)) * Ww + (w - 1)];
    g_xp[((b * 256 + c) * XPH + h) * XPR + w] = v;
}

// ---------------------------------------------------------------------------
// Prep: g_wpt2[cog][ci][tap][cl] = weight[co,ci,tap]*A_w[ci,tap], co=cog*64+cl
//       g_w1t[ci*144 + tap*16 + co] = se_w1[co,ci,tap]
// ---------------------------------------------------------------------------
__global__ void prep_weights(const float* __restrict__ weight,
                             const float* __restrict__ A_w,
                             const float* __restrict__ se_w1) {
    int idx = blockIdx.x * 256 + threadIdx.x;
    if (idx < 589824) {
        int co = idx & 255;
        int tap = (idx >> 8) % 9;
        int ci = idx / 2304;
        g_wpt2[co >> 6][ci][tap][co & 63] =
            weight[co * 2304 + ci * 9 + tap] * A_w[ci * 9 + tap];
    } else if (idx < 589824 + 36864) {
        int i2 = idx - 589824;
        int co = i2 & 15;
        int tap = (i2 >> 4) % 9;
        int ci = i2 / 144;
        g_w1t[i2] = se_w1[co * 2304 + ci * 9 + tap];
    }
}

// ---------------------------------------------------------------------------
// SE conv1: t = relu(conv3x3(x, se_w1))  [8,16,56,56]
// Block 256 = 8 warps; warp = 8 rows x 4 colgroups (8 cols each).
// Each warp handles 2 co (one f32x2 pair). Tile 8x32. Grid (2,7,8).
// Pipelined cp.async double buffer.
// ---------------------------------------------------------------------------
__global__ __launch_bounds__(256) void conv_se1() {
    __shared__ __align__(16) float xs[2][10][36];
    __shared__ __align__(16) float ws[2][9][16];
    int tid = threadIdx.x;
    int cot = tid >> 5;
    int lane = tid & 31;
    int row = lane >> 2;
    int col0 = (lane & 3) << 3;
    int wt = blockIdx.x, ht = blockIdx.y, b = blockIdx.z;
    int h0 = ht * 8, w0 = wt * 32;

    bool isx = tid < 90;
    int xr = tid / 9, xc = (tid % 9) * 4;
    bool isw = (tid >= 90) && (tid < 126);
    int wi = (tid - 90) * 4;
    const float* xpb = g_xp + (long long)b * 256 * XPH * XPR;

    unsigned long long acc[8];
#pragma unroll
    for (int p = 0; p < 8; p++) acc[p] = 0ULL;

    // prologue: load ci=0 into buf 0
    if (isx) cp16(&xs[0][xr][xc], xpb + (h0 + xr) * XPR + (w0 + xc));
    if (isw) cp16(&ws[0][0][wi], g_w1t + wi);
    CP_COMMIT();

    int cur = 0;
    for (int ci = 0; ci < Cc; ci++) {
        CP_WAIT0();
        __syncthreads();
        if (ci + 1 < Cc) {
            int nb = cur ^ 1;
            if (isx)
                cp16(&xs[nb][xr][xc],
                     xpb + (ci + 1) * XPH * XPR + (h0 + xr) * XPR + (w0 + xc));
            if (isw) cp16(&ws[nb][0][wi], g_w1t + (ci + 1) * 144 + wi);
            CP_COMMIT();
        }
        const float(*X)[36] = xs[cur];
        const float(*W)[16] = ws[cur];
#pragma unroll 1
        for (int dy = 0; dy < 3; dy++) {
            unsigned long long xd[10];
#pragma unroll
            for (int p = 0; p < 10; p++) xd[p] = dup2(X[row + dy][col0 + p]);
#pragma unroll
            for (int dx = 0; dx < 3; dx++) {
                unsigned long long wv =
                    *(const unsigned long long*)&W[dy * 3 + dx][cot << 1];
#pragma unroll
                for (int p = 0; p < 8; p++) ffma2(acc[p], wv, xd[p + dx]);
            }
        }
        cur ^= 1;
    }

    int h = h0 + row;
    int co = cot << 1;
    float* t0 = g_t + ((b * 16 + co) * Hh + h) * Ww;
    float* t1 = t0 + Hh * Ww;
#pragma unroll
    for (int p = 0; p < 8; p++) {
        int w = w0 + col0 + p;
        if (w < Ww) {
            t0[w] = fmaxf(__uint_as_float((unsigned)acc[p]), 0.f);
            t1[w] = fmaxf(__uint_as_float((unsigned)(acc[p] >> 32)), 0.f);
        }
    }
}

// ---------------------------------------------------------------------------
// SE conv2 + sigmoid: a = sigmoid(conv3x3(t, se_w2))  [8,56,56]
// ---------------------------------------------------------------------------
__global__ __launch_bounds__(64) void conv_se2(const float* __restrict__ se_w2) {
    __shared__ float ws[144];
    int tid = threadIdx.x;
    int bh = blockIdx.x;
    int b = bh / Hh, h = bh % Hh;
    for (int i = tid; i < 144; i += 64) ws[i] = se_w2[i];
    __syncthreads();
    if (tid >= Ww) return;
    int w = tid;
    float sum = 0.f;
    for (int ci = 0; ci < 16; ci++) {
        const float* tp = g_t + ((b * 16 + ci) * Hh) * Ww;
#pragma unroll
        for (int dy = 0; dy < 3; dy++) {
            int gh = h + dy - 1;
            if (gh < 0 || gh >= Hh) continue;
#pragma unroll
            for (int dx = 0; dx < 3; dx++) {
                int gw = w + dx - 1;
                if (gw < 0 || gw >= Ww) continue;
                sum += tp[gh * Ww + gw] * ws[ci * 9 + dy * 3 + dx];
            }
        }
    }
    g_a[b * Hh * Ww + h * Ww + w] = 1.f / (1.f + __expf(-sum));
}

// ---------------------------------------------------------------------------
// Main conv: out = conv3x3(x, wpt) * a
// Block 256 = 8 warps (co sub-groups of 8 via 4 f32x2 pairs) x 32 spatial.
// Tile: 64 co x (8 rows x 32 cols). Grid (2,7,32): wt, ht, b*4+cog.
// cp.async double-buffered over ci; one barrier per ci.
// ---------------------------------------------------------------------------
__global__ __launch_bounds__(256, 2) void main_conv(float* __restrict__ out) {
    __shared__ __align__(16) float xs[2][10][36];
    __shared__ __align__(16) float ws[2][9][64];
    int tid = threadIdx.x;
    int cot = tid >> 5;
    int lane = tid & 31;
    int row = lane >> 2;
    int col0 = (lane & 3) << 3;
    int wt = blockIdx.x, ht = blockIdx.y;
    int b = blockIdx.z >> 2, cog = blockIdx.z & 3;
    int h0 = ht * 8, w0 = wt * 32;
    int co_base = cog * 64;

    bool isx = tid < 90;
    int xr = tid / 9, xc = (tid % 9) * 4;
    bool isw = (tid >= 90) && (tid < 234);
    int wi = (tid - 90) * 4;
    const float* xpb = g_xp + (long long)b * 256 * XPH * XPR;
    const float* wpb = &g_wpt2[cog][0][0][0];

    unsigned long long acc[4][8];
#pragma unroll
    for (int j = 0; j < 4; j++)
#pragma unroll
        for (int p = 0; p < 8; p++) acc[j][p] = 0ULL;

    if (isx) cp16(&xs[0][xr][xc], xpb + (h0 + xr) * XPR + (w0 + xc));
    if (isw) cp16(&ws[0][0][wi], wpb + wi);
    CP_COMMIT();

    int cur = 0;
    for (int ci = 0; ci < Cc; ci++) {
        CP_WAIT0();
        __syncthreads();
        if (ci + 1 < Cc) {
            int nb = cur ^ 1;
            if (isx)
                cp16(&xs[nb][xr][xc],
                     xpb + (ci + 1) * XPH * XPR + (h0 + xr) * XPR + (w0 + xc));
            if (isw) cp16(&ws[nb][0][wi], wpb + (ci + 1) * 576 + wi);
            CP_COMMIT();
        }
        const float(*X)[36] = xs[cur];
        const float(*W)[64] = ws[cur];
#pragma unroll 1
        for (int dy = 0; dy < 3; dy++) {
            unsigned long long xd[10];
#pragma unroll
            for (int p = 0; p < 10; p++) xd[p] = dup2(X[row + dy][col0 + p]);
#pragma unroll
            for (int dx = 0; dx < 3; dx++) {
                const unsigned long long* w2 =
                    (const unsigned long long*)&W[dy * 3 + dx][cot << 3];
                unsigned long long wv0 = w2[0], wv1 = w2[1], wv2 = w2[2],
                                  wv3 = w2[3];
#pragma unroll
                for (int p = 0; p < 8; p++) {
                    unsigned long long xv = xd[p + dx];
                    ffma2(acc[0][p], wv0, xv);
                    ffma2(acc[1][p], wv1, xv);
                    ffma2(acc[2][p], wv2, xv);
                    ffma2(acc[3][p], wv3, xv);
                }
            }
        }
        cur ^= 1;
    }

    // Epilogue: unpack pairs, multiply by attention map, store.
    int h = h0 + row;
    const float* ab = g_a + b * Hh * Ww + h * Ww;
    float av[8];
#pragma unroll
    for (int p = 0; p < 8; p++) {
        int w = w0 + col0 + p;
        av[p] = (w < Ww) ? ab[w] : 0.f;
    }
#pragma unroll
    for (int j2 = 0; j2 < 4; j2++) {
        int co = co_base + (cot << 3) + (j2 << 1);
        float* o0 = out + ((b * Cc + co) * Hh + h) * Ww;
        float* o1 = o0 + Hh * Ww;
#pragma unroll
        for (int p = 0; p < 8; p++) {
            int w = w0 + col0 + p;
            if (w < Ww) {
                o0[w] = __uint_as_float((unsigned)acc[j2][p]) * av[p];
                o1[w] = __uint_as_float((unsigned)(acc[j2][p] >> 32)) * av[p];
            }
        }
    }
}

// ---------------------------------------------------------------------------
extern "C" void kernel_launch(void* const* d_in, const int* in_sizes, int n_in,
                              void* d_out, int out_size) {
    const float* x = (const float*)d_in[0];       // [8,256,56,56]
    const float* weight = (const float*)d_in[1];  // [256,256,3,3]
    const float* A_w = (const float*)d_in[2];     // [1,256,3,3]
    const float* se_w1 = (const float*)d_in[3];   // [16,256,3,3]
    const float* se_w2 = (const float*)d_in[4];   // [1,16,3,3]
    float* out = (float*)d_out;                   // [8,256,56,56]

    pad_x<<<(8 * 256 * XPH * XPH + 255) / 256, 256>>>(x);
    prep_weights<<<(589824 + 36864 + 255) / 256, 256>>>(weight, A_w, se_w1);
    conv_se1<<<dim3(2, 7, 8), 256>>>();
    conv_se2<<<8 * Hh, 64>>>(se_w2);
    main_conv<<<dim3(2, 7, 32), 256>>>(out);
}